// round 1
// baseline (speedup 1.0000x reference)
#include <cuda_runtime.h>
#include <cuda_bf16.h>
#include <math.h>

// Problem constants (match reference)
#define NN 100000
#define DD 128
#define FE 4

// Scratch (static device globals — no allocation allowed)
__device__ float g_h[NN * DD];      // normalized feats
__device__ float g_agg[NN * DD];    // message aggregation, then rst in-place
__device__ float g_norm[NN];
__device__ int   g_deg[NN];         // out-degree over src_E
__device__ int   g_indeg[NN];       // total in-degree (main + acc)
__device__ float4 g_efsum[NN];      // sum of edge feats into dst (main edges)

__device__ __forceinline__ void red_add_v4(float* p, float x, float y, float z, float w) {
    asm volatile("red.global.add.v4.f32 [%0], {%1,%2,%3,%4};"
                 :: "l"(p), "f"(x), "f"(y), "f"(z), "f"(w) : "memory");
}

// ---------------------------------------------------------------- zero scratch
__global__ void k_zero(int n) {
    int stride = gridDim.x * blockDim.x;
    int i = blockIdx.x * blockDim.x + threadIdx.x;
    int total4 = n * (DD / 4);
    float4 z = make_float4(0.f, 0.f, 0.f, 0.f);
    for (int idx = i; idx < total4; idx += stride)
        ((float4*)g_agg)[idx] = z;
    for (int idx = i; idx < n; idx += stride) {
        g_deg[idx] = 0;
        g_indeg[idx] = 0;
        g_efsum[idx] = z;
    }
}

// ------------------------------------------------- degree / indegree / efsum
__global__ void k_count(const int* __restrict__ srcE, const int* __restrict__ dstE,
                        const float4* __restrict__ ef,
                        const int* __restrict__ dstA,
                        int eM, int eA) {
    int stride = gridDim.x * blockDim.x;
    for (int e = blockIdx.x * blockDim.x + threadIdx.x; e < eM; e += stride) {
        atomicAdd(&g_deg[srcE[e]], 1);
        int d = dstE[e];
        atomicAdd(&g_indeg[d], 1);
        float4 f = ef[e];
        red_add_v4((float*)&g_efsum[d], f.x, f.y, f.z, f.w);
    }
    for (int e = blockIdx.x * blockDim.x + threadIdx.x; e < eA; e += stride) {
        atomicAdd(&g_indeg[dstA[e]], 1);
    }
}

// --------------------------------------------------------------- norm & h
__global__ void k_hnorm(const float4* __restrict__ feats, int n) {
    int gtid = blockIdx.x * blockDim.x + threadIdx.x;
    int warp = gtid >> 5;
    int lane = gtid & 31;
    int nwarps = (gridDim.x * blockDim.x) >> 5;
    for (int node = warp; node < n; node += nwarps) {
        int deg = g_deg[node];
        float nrm = (deg > 0) ? rsqrtf((float)deg) : 0.f;
        if (lane == 0) g_norm[node] = nrm;
        float4 f = feats[node * 32 + lane];
        float4 hv = make_float4(f.x * nrm, f.y * nrm, f.z * nrm, f.w * nrm);
        ((float4*)g_h)[node * 32 + lane] = hv;
    }
}

// ------------------------------------------- main edge scatter: att*h[src] -> agg[dst]
__global__ void k_scatter_main(const int* __restrict__ src, const int* __restrict__ dst,
                               const float4* __restrict__ ef,
                               const float* __restrict__ W_att, const float* __restrict__ b_att,
                               int eM) {
    int gtid = blockIdx.x * blockDim.x + threadIdx.x;
    int e = gtid >> 5;
    int lane = gtid & 31;
    if (e >= eM) return;
    int s = src[e];            // warp-uniform broadcast loads
    int d = dst[e];
    float4 f = ef[e];
    float x = W_att[0] * f.x + W_att[1] * f.y + W_att[2] * f.z + W_att[3] * f.w + b_att[0];
    float att = 1.f / (1.f + __expf(-x));
    float4 hv = ((const float4*)g_h)[s * 32 + lane];
    red_add_v4(&g_agg[d * DD + lane * 4], att * hv.x, att * hv.y, att * hv.z, att * hv.w);
}

// ------------------------------------------- account edge scatter: att0*h[src] -> agg[dst]
__global__ void k_scatter_acc(const int* __restrict__ src, const int* __restrict__ dst,
                              const float* __restrict__ b_att, int eA) {
    int gtid = blockIdx.x * blockDim.x + threadIdx.x;
    int e = gtid >> 5;
    int lane = gtid & 31;
    if (e >= eA) return;
    float att = 1.f / (1.f + __expf(-b_att[0]));
    int s = src[e];
    int d = dst[e];
    float4 hv = ((const float4*)g_h)[s * 32 + lane];
    red_add_v4(&g_agg[d * DD + lane * 4], att * hv.x, att * hv.y, att * hv.z, att * hv.w);
}

// ---------------------- per-node epilogue: rst = (agg + W_edge@efsum + indeg*(b_edge+h))*norm
__global__ void k_rst(const float4* __restrict__ W_edge,   // [DD][4] rows as float4
                      const float4* __restrict__ b_edge,   // [DD] as float4*32
                      int n) {
    int gtid = blockIdx.x * blockDim.x + threadIdx.x;
    int warp = gtid >> 5;
    int lane = gtid & 31;
    if (warp >= n) return;
    int node = warp;
    float nrm = g_norm[node];
    float ind = (float)g_indeg[node];
    float4 efs = g_efsum[node];
    float4 agg = ((float4*)g_agg)[node * 32 + lane];
    float4 hv  = ((const float4*)g_h)[node * 32 + lane];
    float4 be  = b_edge[lane];
    float4 out;
    {
        float4 w = W_edge[lane * 4 + 0];
        float wef = w.x * efs.x + w.y * efs.y + w.z * efs.z + w.w * efs.w;
        out.x = (agg.x + wef + ind * (be.x + hv.x)) * nrm;
    }
    {
        float4 w = W_edge[lane * 4 + 1];
        float wef = w.x * efs.x + w.y * efs.y + w.z * efs.z + w.w * efs.w;
        out.y = (agg.y + wef + ind * (be.y + hv.y)) * nrm;
    }
    {
        float4 w = W_edge[lane * 4 + 2];
        float wef = w.x * efs.x + w.y * efs.y + w.z * efs.z + w.w * efs.w;
        out.z = (agg.z + wef + ind * (be.z + hv.z)) * nrm;
    }
    {
        float4 w = W_edge[lane * 4 + 3];
        float wef = w.x * efs.x + w.y * efs.y + w.z * efs.z + w.w * efs.w;
        out.w = (agg.w + wef + ind * (be.w + hv.w)) * nrm;
    }
    ((float4*)g_agg)[node * 32 + lane] = out;   // rst written in place
}

// -------------------- SGEMM: out = rst@W_msg^T + feats@W_skip^T + (b_msg + b_skip)
// Virtual A = [rst | feats] (N x 256), virtual B = [W_msg^T ; W_skip^T] (256 x 128)
#define BM 128
#define BK 16
#define BN 128
#define TM 8
#define TN 8

__global__ __launch_bounds__(256) void k_gemm(
    const float* __restrict__ A1,      // feats
    const float* __restrict__ B0,      // W_msg [j][k]
    const float* __restrict__ B1,      // W_skip [j][k]
    const float* __restrict__ b0, const float* __restrict__ b1,
    float* __restrict__ C, int n) {
    __shared__ float As[BM * (BK + 1)];
    __shared__ float Bs[BK * (BN + 4)];
    const float* A0 = g_agg;          // rst
    int tid = threadIdx.x;
    int tx = tid & 15;                // col group (cols tx + 16*c)
    int ty = tid >> 4;                // row group (rows ty*8 + r)
    int row0 = blockIdx.x * BM;

    float acc[TM][TN];
#pragma unroll
    for (int r = 0; r < TM; r++)
#pragma unroll
        for (int c = 0; c < TN; c++) acc[r][c] = 0.f;

    int kkl = tid & 15;               // A-load: k within chunk
    int rb = tid >> 4;                // A-load: base row

    for (int chunk = 0; chunk < 16; ++chunk) {
        const float* Aptr = (chunk < 8) ? A0 : A1;
        const float* Bptr = (chunk < 8) ? B0 : B1;
        int k0 = (chunk & 7) * BK;
        // A tile: 128 x 16
#pragma unroll
        for (int i = 0; i < 8; ++i) {
            int r = rb + i * 16;
            int grow = row0 + r;
            float v = (grow < n) ? Aptr[grow * DD + k0 + kkl] : 0.f;
            As[r * (BK + 1) + kkl] = v;
        }
        // B tile: 16 x 128 (transposed from [j][k] storage)
#pragma unroll
        for (int i = 0; i < 8; ++i) {
            int idx = tid + i * 256;
            int kl = idx & 15;
            int j = idx >> 4;
            Bs[kl * (BN + 4) + j] = Bptr[j * DD + k0 + kl];
        }
        __syncthreads();
#pragma unroll
        for (int kk = 0; kk < BK; ++kk) {
            float a[TM], b[TN];
#pragma unroll
            for (int r = 0; r < TM; ++r) a[r] = As[(ty * TM + r) * (BK + 1) + kk];
#pragma unroll
            for (int c = 0; c < TN; ++c) b[c] = Bs[kk * (BN + 4) + tx + c * 16];
#pragma unroll
            for (int r = 0; r < TM; ++r)
#pragma unroll
                for (int c = 0; c < TN; ++c)
                    acc[r][c] += a[r] * b[c];
        }
        __syncthreads();
    }
#pragma unroll
    for (int r = 0; r < TM; ++r) {
        int row = row0 + ty * TM + r;
        if (row < n) {
#pragma unroll
            for (int c = 0; c < TN; ++c) {
                int col = tx + c * 16;
                C[row * DD + col] = acc[r][c] + b0[col] + b1[col];
            }
        }
    }
}

extern "C" void kernel_launch(void* const* d_in, const int* in_sizes, int n_in,
                              void* d_out, int out_size) {
    const float* feats      = (const float*)d_in[0];
    const float* edge_feats = (const float*)d_in[1];
    const int*   src_E      = (const int*)d_in[2];
    const int*   dst_E      = (const int*)d_in[3];
    const int*   src_acc    = (const int*)d_in[4];
    const int*   dst_acc    = (const int*)d_in[5];
    const float* W_skip     = (const float*)d_in[6];
    const float* b_skip     = (const float*)d_in[7];
    const float* W_msg      = (const float*)d_in[8];
    const float* b_msg      = (const float*)d_in[9];
    const float* W_edge     = (const float*)d_in[10];
    const float* b_edge     = (const float*)d_in[11];
    const float* W_att      = (const float*)d_in[12];
    const float* b_att      = (const float*)d_in[13];
    float* out = (float*)d_out;

    int n  = in_sizes[0] / DD;
    int eM = in_sizes[2];
    int eA = in_sizes[4];

    // 1. zero scratch
    k_zero<<<12500, 256>>>(n);
    // 2. counts / efsum
    k_count<<<(eM + 255) / 256, 256>>>(src_E, dst_E, (const float4*)edge_feats, dst_acc, eM, eA);
    // 3. norm & h
    k_hnorm<<<(n * 32 + 255) / 256, 256>>>((const float4*)feats, n);
    // 4. main edge scatter (warp per edge)
    k_scatter_main<<<(eM * 32 + 255) / 256, 256>>>(src_E, dst_E, (const float4*)edge_feats,
                                                   W_att, b_att, eM);
    // 5. account edge scatter
    k_scatter_acc<<<(eA * 32 + 255) / 256, 256>>>(src_acc, dst_acc, b_att, eA);
    // 6. per-node epilogue -> rst (in place in g_agg)
    k_rst<<<(n * 32 + 255) / 256, 256>>>((const float4*)W_edge, (const float4*)b_edge, n);
    // 7. fused double-GEMM epilogue
    k_gemm<<<(n + BM - 1) / BM, 256>>>(feats, W_msg, W_skip, b_msg, b_skip, out, n);
}

// round 2
// speedup vs baseline: 1.4121x; 1.4121x over previous
#include <cuda_runtime.h>
#include <math.h>

#define NN 100000
#define DD 128
#define EMAXM 1600000
#define EMAXT 1800000
#define NBMAX 512

// ---- static scratch (no allocation allowed) ----
__device__ float  g_agg[NN * DD];     // gathered messages, read by GEMM as A0
__device__ float  g_norm[NN];
__device__ int    g_deg[NN];
__device__ int    g_indeg[NN];
__device__ float4 g_efsum[NN];
__device__ int    g_off[NN];
__device__ int    g_cursor[NN];
__device__ int    g_bsum[NBMAX];
__device__ int    g_boff[NBMAX];
__device__ float  g_att[EMAXM];       // per-main-edge attention
__device__ int    g_esrc[EMAXT];      // CSR: src per edge, grouped by dst
__device__ float  g_eatt[EMAXT];      // CSR: att per edge, grouped by dst

__device__ __forceinline__ void red_add_v4(float* p, float x, float y, float z, float w) {
    asm volatile("red.global.add.v4.f32 [%0], {%1,%2,%3,%4};"
                 :: "l"(p), "f"(x), "f"(y), "f"(z), "f"(w) : "memory");
}
__device__ __forceinline__ unsigned long long pack2(float x, float y) {
    unsigned long long r;
    asm("mov.b64 %0, {%1,%2};" : "=l"(r) : "r"(__float_as_uint(x)), "r"(__float_as_uint(y)));
    return r;
}
__device__ __forceinline__ void unpack2(unsigned long long v, float& x, float& y) {
    unsigned int a, b;
    asm("mov.b64 {%0,%1}, %2;" : "=r"(a), "=r"(b) : "l"(v));
    x = __uint_as_float(a); y = __uint_as_float(b);
}
__device__ __forceinline__ void ffma2(unsigned long long& d, unsigned long long a, unsigned long long b) {
    asm("fma.rn.f32x2 %0, %1, %2, %0;" : "+l"(d) : "l"(a), "l"(b));
}

// -------------------------------------------------------- zero small scratch
__global__ void k_init(int n) {
    int stride = gridDim.x * blockDim.x;
    for (int i = blockIdx.x * blockDim.x + threadIdx.x; i < n; i += stride) {
        g_deg[i] = 0;
        g_indeg[i] = 0;
        g_efsum[i] = make_float4(0.f, 0.f, 0.f, 0.f);
    }
}

// ------------------------- degrees, efsum, per-edge attention (main edges)
__global__ void k_count(const int* __restrict__ srcE, const int* __restrict__ dstE,
                        const float4* __restrict__ ef, const int* __restrict__ dstA,
                        const float* __restrict__ W_att, const float* __restrict__ b_att,
                        int eM, int eA) {
    int stride = gridDim.x * blockDim.x;
    int i0 = blockIdx.x * blockDim.x + threadIdx.x;
    float w0 = W_att[0], w1 = W_att[1], w2 = W_att[2], w3 = W_att[3], bb = b_att[0];
    for (int e = i0; e < eM; e += stride) {
        atomicAdd(&g_deg[srcE[e]], 1);
        int d = dstE[e];
        atomicAdd(&g_indeg[d], 1);
        float4 f = ef[e];
        red_add_v4((float*)&g_efsum[d], f.x, f.y, f.z, f.w);
        float x = w0 * f.x + w1 * f.y + w2 * f.z + w3 * f.w + bb;
        g_att[e] = 1.f / (1.f + __expf(-x));
    }
    for (int e = i0; e < eA; e += stride)
        atomicAdd(&g_indeg[dstA[e]], 1);
}

// ---------------- scan pass 1: per-block indeg sums; also compute norm
__global__ void k_scan1(int n) {
    int t = blockIdx.x * 256 + threadIdx.x;
    int v = (t < n) ? g_indeg[t] : 0;
    if (t < n) {
        int dg = g_deg[t];
        g_norm[t] = (dg > 0) ? rsqrtf((float)dg) : 0.f;
    }
    __shared__ int sh[256];
    sh[threadIdx.x] = v;
    __syncthreads();
    for (int o = 128; o > 0; o >>= 1) {
        if (threadIdx.x < o) sh[threadIdx.x] += sh[threadIdx.x + o];
        __syncthreads();
    }
    if (threadIdx.x == 0) g_bsum[blockIdx.x] = sh[0];
}

// ---------------- scan pass 2: exclusive scan of block sums (1 block)
__global__ void k_scan2(int nb) {
    __shared__ int sh[NBMAX];
    int t = threadIdx.x;
    int v = (t < nb) ? g_bsum[t] : 0;
    sh[t] = v;
    __syncthreads();
    for (int o = 1; o < NBMAX; o <<= 1) {
        int x = (t >= o) ? sh[t - o] : 0;
        __syncthreads();
        sh[t] += x;
        __syncthreads();
    }
    if (t < nb) g_boff[t] = sh[t] - v;
}

// ---------------- scan pass 3: per-element exclusive scan -> off, cursor
__global__ void k_scan3(int n) {
    __shared__ int sh[256];
    int t = blockIdx.x * 256 + threadIdx.x;
    int v = (t < n) ? g_indeg[t] : 0;
    sh[threadIdx.x] = v;
    __syncthreads();
    for (int o = 1; o < 256; o <<= 1) {
        int x = (threadIdx.x >= o) ? sh[threadIdx.x - o] : 0;
        __syncthreads();
        sh[threadIdx.x] += x;
        __syncthreads();
    }
    if (t < n) {
        int off = sh[threadIdx.x] - v + g_boff[blockIdx.x];
        g_off[t] = off;
        g_cursor[t] = off;
    }
}

// ---------------- fill CSR buckets (both edge types)
__global__ void k_fill(const int* __restrict__ srcE, const int* __restrict__ dstE,
                       const int* __restrict__ srcA, const int* __restrict__ dstA,
                       const float* __restrict__ b_att, int eM, int eA) {
    int i = blockIdx.x * blockDim.x + threadIdx.x;
    int tot = eM + eA;
    if (i >= tot) return;
    int s, d; float a;
    if (i < eM) {
        s = srcE[i]; d = dstE[i]; a = g_att[i];
    } else {
        int j = i - eM;
        s = srcA[j]; d = dstA[j];
        a = 1.f / (1.f + __expf(-b_att[0]));
    }
    int pos = atomicAdd(&g_cursor[d], 1);
    g_esrc[pos] = s;
    g_eatt[pos] = a;
}

// ---------------- gather: warp per dst node, no atomics
__global__ void k_gather(const float4* __restrict__ feats, int n) {
    int gtid = blockIdx.x * blockDim.x + threadIdx.x;
    int v = gtid >> 5;
    int lane = gtid & 31;
    if (v >= n) return;
    int off = g_off[v];
    int cnt = g_indeg[v];
    float4 acc = make_float4(0.f, 0.f, 0.f, 0.f);
    for (int base = 0; base < cnt; base += 32) {
        int m = cnt - base; if (m > 32) m = 32;
        int s = 0; float c = 0.f;
        if (lane < m) {
            s = g_esrc[off + base + lane];
            c = g_eatt[off + base + lane] * g_norm[s];
        }
#pragma unroll 4
        for (int i = 0; i < m; i++) {
            int   si = __shfl_sync(0xffffffffu, s, i);
            float ci = __shfl_sync(0xffffffffu, c, i);
            float4 f = feats[si * 32 + lane];
            acc.x = fmaf(ci, f.x, acc.x);
            acc.y = fmaf(ci, f.y, acc.y);
            acc.z = fmaf(ci, f.z, acc.z);
            acc.w = fmaf(ci, f.w, acc.w);
        }
    }
    ((float4*)g_agg)[v * 32 + lane] = acc;
}

// -------------------- fused rst + double GEMM with f32x2 packed FMA
// out = rst@W_msg^T + feats@W_skip^T + (b_msg+b_skip)
// rst[row][k] = (agg[row][k] + W_edge[k]·efs[row] + ind[row]*(b_edge[k] + feats[row][k]*nrm[row])) * nrm[row]
#define BM 128
#define BK 16
#define SA (BK * 132)

__global__ __launch_bounds__(256) void k_gemm(
    const float* __restrict__ feats,
    const float* __restrict__ Wmsg, const float* __restrict__ Wskip,
    const float* __restrict__ bmsg, const float* __restrict__ bskip,
    const float4* __restrict__ Wedge, const float* __restrict__ bedge,
    float* __restrict__ C, int n) {
    __shared__ float As[SA];          // [k][row], stride 132
    __shared__ float Bs[SA];          // [k][col], stride 132
    __shared__ float4 sWe[DD];
    __shared__ float  sBe[DD];
    __shared__ float  sBias[DD];

    int tid = threadIdx.x;
    int tx = tid & 15;                // cols tx*4..+3 and 64+tx*4..+3
    int ty = tid >> 4;                // rows ty*8..+7
    int row0 = blockIdx.x * BM;

    if (tid < DD) {
        sWe[tid] = Wedge[tid];
        sBe[tid] = bedge[tid];
        sBias[tid] = bmsg[tid] + bskip[tid];
    }

    // per-thread A-load row scalars (rows rb + 16*i)
    int kkl = tid & 15;
    int rb = tid >> 4;
    float4 efs8[8];
    float  ind8[8], nrm8[8];
#pragma unroll
    for (int i = 0; i < 8; i++) {
        int grow = row0 + rb + i * 16;
        if (grow < n) {
            efs8[i] = g_efsum[grow];
            ind8[i] = (float)g_indeg[grow];
            nrm8[i] = g_norm[grow];
        } else {
            efs8[i] = make_float4(0.f, 0.f, 0.f, 0.f);
            ind8[i] = 0.f; nrm8[i] = 0.f;
        }
    }

    unsigned long long accP[8][4];
#pragma unroll
    for (int r = 0; r < 8; r++)
#pragma unroll
        for (int p = 0; p < 4; p++) accP[r][p] = 0ULL;

    for (int chunk = 0; chunk < 16; ++chunk) {
        int k0 = (chunk & 7) * BK;
        int kg = k0 + kkl;
        const float* Bptr = (chunk < 8) ? Wmsg : Wskip;
        // ---- A tile ----
        if (chunk < 8) {
            float4 w = sWe[kg];
            float be = sBe[kg];
#pragma unroll
            for (int i = 0; i < 8; i++) {
                int r = rb + i * 16;
                int grow = row0 + r;
                float val = 0.f;
                if (grow < n) {
                    float a = g_agg[grow * DD + kg];
                    float fv = feats[grow * DD + kg];
                    float wef = w.x * efs8[i].x + w.y * efs8[i].y + w.z * efs8[i].z + w.w * efs8[i].w;
                    val = (a + wef + ind8[i] * (be + fv * nrm8[i])) * nrm8[i];
                }
                As[kkl * 132 + r] = val;
            }
        } else {
#pragma unroll
            for (int i = 0; i < 8; i++) {
                int r = rb + i * 16;
                int grow = row0 + r;
                As[kkl * 132 + r] = (grow < n) ? feats[grow * DD + kg] : 0.f;
            }
        }
        // ---- B tile (transpose from [j][k]) ----
#pragma unroll
        for (int i = 0; i < 8; i++) {
            int idx = tid + i * 256;
            int kl = idx & 15;
            int j = idx >> 4;
            Bs[kl * 132 + j] = Bptr[j * DD + k0 + kl];
        }
        __syncthreads();
        // ---- inner product ----
#pragma unroll
        for (int kk = 0; kk < BK; ++kk) {
            float4 aA = *(const float4*)&As[kk * 132 + ty * 8];
            float4 aB = *(const float4*)&As[kk * 132 + ty * 8 + 4];
            unsigned long long bp0 = *(const unsigned long long*)&Bs[kk * 132 + tx * 4];
            unsigned long long bp1 = *(const unsigned long long*)&Bs[kk * 132 + tx * 4 + 2];
            unsigned long long bp2 = *(const unsigned long long*)&Bs[kk * 132 + 64 + tx * 4];
            unsigned long long bp3 = *(const unsigned long long*)&Bs[kk * 132 + 64 + tx * 4 + 2];
            float av[8] = {aA.x, aA.y, aA.z, aA.w, aB.x, aB.y, aB.z, aB.w};
#pragma unroll
            for (int r = 0; r < 8; r++) {
                unsigned long long ar = pack2(av[r], av[r]);
                ffma2(accP[r][0], ar, bp0);
                ffma2(accP[r][1], ar, bp1);
                ffma2(accP[r][2], ar, bp2);
                ffma2(accP[r][3], ar, bp3);
            }
        }
        __syncthreads();
    }

    // ---- store ----
    float bias0x = sBias[tx * 4 + 0], bias0y = sBias[tx * 4 + 1];
    float bias0z = sBias[tx * 4 + 2], bias0w = sBias[tx * 4 + 3];
    float bias1x = sBias[64 + tx * 4 + 0], bias1y = sBias[64 + tx * 4 + 1];
    float bias1z = sBias[64 + tx * 4 + 2], bias1w = sBias[64 + tx * 4 + 3];
#pragma unroll
    for (int r = 0; r < 8; r++) {
        int row = row0 + ty * 8 + r;
        if (row < n) {
            float4 o0, o1;
            unpack2(accP[r][0], o0.x, o0.y);
            unpack2(accP[r][1], o0.z, o0.w);
            unpack2(accP[r][2], o1.x, o1.y);
            unpack2(accP[r][3], o1.z, o1.w);
            o0.x += bias0x; o0.y += bias0y; o0.z += bias0z; o0.w += bias0w;
            o1.x += bias1x; o1.y += bias1y; o1.z += bias1z; o1.w += bias1w;
            ((float4*)C)[row * 32 + tx] = o0;
            ((float4*)C)[row * 32 + 16 + tx] = o1;
        }
    }
}

extern "C" void kernel_launch(void* const* d_in, const int* in_sizes, int n_in,
                              void* d_out, int out_size) {
    const float* feats      = (const float*)d_in[0];
    const float* edge_feats = (const float*)d_in[1];
    const int*   src_E      = (const int*)d_in[2];
    const int*   dst_E      = (const int*)d_in[3];
    const int*   src_acc    = (const int*)d_in[4];
    const int*   dst_acc    = (const int*)d_in[5];
    const float* W_skip     = (const float*)d_in[6];
    const float* b_skip     = (const float*)d_in[7];
    const float* W_msg      = (const float*)d_in[8];
    const float* b_msg      = (const float*)d_in[9];
    const float* W_edge     = (const float*)d_in[10];
    const float* b_edge     = (const float*)d_in[11];
    const float* W_att      = (const float*)d_in[12];
    const float* b_att      = (const float*)d_in[13];
    float* out = (float*)d_out;

    int n  = in_sizes[0] / DD;
    int eM = in_sizes[2];
    int eA = in_sizes[4];
    int nb = (n + 255) / 256;

    k_init<<<128, 512>>>(n);
    k_count<<<2048, 512>>>(src_E, dst_E, (const float4*)edge_feats, dst_acc,
                           W_att, b_att, eM, eA);
    k_scan1<<<nb, 256>>>(n);
    k_scan2<<<1, NBMAX>>>(nb);
    k_scan3<<<nb, 256>>>(n);
    k_fill<<<(eM + eA + 255) / 256, 256>>>(src_E, dst_E, src_acc, dst_acc, b_att, eM, eA);
    k_gather<<<(n * 32 + 255) / 256, 256>>>((const float4*)feats, n);
    k_gemm<<<(n + BM - 1) / BM, 256>>>(feats, W_msg, W_skip, b_msg, b_skip,
                                       (const float4*)W_edge, b_edge, out, n);
}

// round 4
// speedup vs baseline: 1.9638x; 1.3907x over previous
#include <cuda_runtime.h>
#include <cuda_bf16.h>
#include <math.h>
#include <cstdint>

#define NN 100000
#define DD 128
#define EMAXM 1600000
#define EMAXT 1800000
#define NBMAX 512

// ---- static scratch (no allocation allowed) ----
__device__ float  g_agg[NN * DD];
__device__ float  g_norm[NN];
__device__ int    g_deg[NN];
__device__ int    g_indeg[NN];
__device__ float4 g_efsum[NN];
__device__ int    g_off[NN];
__device__ int    g_cursor[NN];
__device__ int    g_bsum[NBMAX];
__device__ int    g_boff[NBMAX];
__device__ float  g_att[EMAXM];
__device__ int    g_esrc[EMAXT];
__device__ float  g_eatt[EMAXT];
// B prepacked as 4 tiles (phase x kchunk), each tile = [hi 16KB][lo 16KB]
// in the exact swizzled smem image the GEMM uses.
__device__ __align__(16) uint8_t g_Bt[4 * 32768];

__device__ __forceinline__ void red_add_v4(float* p, float x, float y, float z, float w) {
    asm volatile("red.global.add.v4.f32 [%0], {%1,%2,%3,%4};"
                 :: "l"(p), "f"(x), "f"(y), "f"(z), "f"(w) : "memory");
}
__device__ __forceinline__ uint32_t smem_u32(const void* p) {
    uint32_t a;
    asm("{ .reg .u64 t; cvta.to.shared.u64 t, %1; cvt.u32.u64 %0, t; }" : "=r"(a) : "l"(p));
    return a;
}
// swizzled byte offset inside a 128-row x 64-col bf16 tile (128B rows)
__device__ __forceinline__ uint32_t swz(int row, int col) {
    return (uint32_t)(row * 128 + ((((col >> 3) ^ (row & 7)) << 4)) + ((col & 7) << 1));
}

// ======================= graph-prep kernels (unchanged from R2) =============
__global__ void k_init(int n) {
    int stride = gridDim.x * blockDim.x;
    for (int i = blockIdx.x * blockDim.x + threadIdx.x; i < n; i += stride) {
        g_deg[i] = 0;
        g_indeg[i] = 0;
        g_efsum[i] = make_float4(0.f, 0.f, 0.f, 0.f);
    }
}

__global__ void k_prepB(const float* __restrict__ Wmsg, const float* __restrict__ Wskip) {
    int w = blockIdx.x * blockDim.x + threadIdx.x;
    if (w >= 16384) return;
    int phase = w >> 13;
    int j = (w >> 6) & 127;
    int kp = w & 63;
    int k = kp * 2;
    const float* W = phase ? Wskip : Wmsg;
    float v0 = W[j * DD + k], v1 = W[j * DD + k + 1];
    __nv_bfloat16 h0 = __float2bfloat16(v0), h1 = __float2bfloat16(v1);
    float l0 = v0 - __bfloat162float(h0), l1 = v1 - __bfloat162float(h1);
    __nv_bfloat16 q0 = __float2bfloat16(l0), q1 = __float2bfloat16(l1);
    uint32_t hw = (uint32_t)__bfloat16_as_ushort(h0) | ((uint32_t)__bfloat16_as_ushort(h1) << 16);
    uint32_t lw = (uint32_t)__bfloat16_as_ushort(q0) | ((uint32_t)__bfloat16_as_ushort(q1) << 16);
    int kc2 = k >> 6;
    int kin = k & 63;
    int tile = phase * 2 + kc2;
    uint32_t off = swz(j, kin);
    *(uint32_t*)(g_Bt + tile * 32768 + off) = hw;
    *(uint32_t*)(g_Bt + tile * 32768 + 16384 + off) = lw;
}

__global__ void k_count(const int* __restrict__ srcE, const int* __restrict__ dstE,
                        const float4* __restrict__ ef, const int* __restrict__ dstA,
                        const float* __restrict__ W_att, const float* __restrict__ b_att,
                        int eM, int eA) {
    int stride = gridDim.x * blockDim.x;
    int i0 = blockIdx.x * blockDim.x + threadIdx.x;
    float w0 = W_att[0], w1 = W_att[1], w2 = W_att[2], w3 = W_att[3], bb = b_att[0];
    for (int e = i0; e < eM; e += stride) {
        atomicAdd(&g_deg[srcE[e]], 1);
        int d = dstE[e];
        atomicAdd(&g_indeg[d], 1);
        float4 f = ef[e];
        red_add_v4((float*)&g_efsum[d], f.x, f.y, f.z, f.w);
        float x = w0 * f.x + w1 * f.y + w2 * f.z + w3 * f.w + bb;
        g_att[e] = 1.f / (1.f + __expf(-x));
    }
    for (int e = i0; e < eA; e += stride)
        atomicAdd(&g_indeg[dstA[e]], 1);
}

__global__ void k_scan1(int n) {
    int t = blockIdx.x * 256 + threadIdx.x;
    int v = (t < n) ? g_indeg[t] : 0;
    if (t < n) {
        int dg = g_deg[t];
        g_norm[t] = (dg > 0) ? rsqrtf((float)dg) : 0.f;
    }
    __shared__ int sh[256];
    sh[threadIdx.x] = v;
    __syncthreads();
    for (int o = 128; o > 0; o >>= 1) {
        if (threadIdx.x < o) sh[threadIdx.x] += sh[threadIdx.x + o];
        __syncthreads();
    }
    if (threadIdx.x == 0) g_bsum[blockIdx.x] = sh[0];
}

__global__ void k_scan2(int nb) {
    __shared__ int sh[NBMAX];
    int t = threadIdx.x;
    int v = (t < nb) ? g_bsum[t] : 0;
    sh[t] = v;
    __syncthreads();
    for (int o = 1; o < NBMAX; o <<= 1) {
        int x = (t >= o) ? sh[t - o] : 0;
        __syncthreads();
        sh[t] += x;
        __syncthreads();
    }
    if (t < nb) g_boff[t] = sh[t] - v;
}

__global__ void k_scan3(int n) {
    __shared__ int sh[256];
    int t = blockIdx.x * 256 + threadIdx.x;
    int v = (t < n) ? g_indeg[t] : 0;
    sh[threadIdx.x] = v;
    __syncthreads();
    for (int o = 1; o < 256; o <<= 1) {
        int x = (threadIdx.x >= o) ? sh[threadIdx.x - o] : 0;
        __syncthreads();
        sh[threadIdx.x] += x;
        __syncthreads();
    }
    if (t < n) {
        int off = sh[threadIdx.x] - v + g_boff[blockIdx.x];
        g_off[t] = off;
        g_cursor[t] = off;
    }
}

__global__ void k_fill(const int* __restrict__ srcE, const int* __restrict__ dstE,
                       const int* __restrict__ srcA, const int* __restrict__ dstA,
                       const float* __restrict__ b_att, int eM, int eA) {
    int i = blockIdx.x * blockDim.x + threadIdx.x;
    int tot = eM + eA;
    if (i >= tot) return;
    int s, d; float a;
    if (i < eM) {
        s = srcE[i]; d = dstE[i]; a = g_att[i];
    } else {
        int j = i - eM;
        s = srcA[j]; d = dstA[j];
        a = 1.f / (1.f + __expf(-b_att[0]));
    }
    int pos = atomicAdd(&g_cursor[d], 1);
    g_esrc[pos] = s;
    g_eatt[pos] = a;
}

__global__ void k_gather(const float4* __restrict__ feats, int n) {
    int gtid = blockIdx.x * blockDim.x + threadIdx.x;
    int v = gtid >> 5;
    int lane = gtid & 31;
    if (v >= n) return;
    int off = g_off[v];
    int cnt = g_indeg[v];
    float4 acc = make_float4(0.f, 0.f, 0.f, 0.f);
    for (int base = 0; base < cnt; base += 32) {
        int m = cnt - base; if (m > 32) m = 32;
        int s = 0; float c = 0.f;
        if (lane < m) {
            s = g_esrc[off + base + lane];
            c = g_eatt[off + base + lane] * g_norm[s];
        }
#pragma unroll 4
        for (int i = 0; i < m; i++) {
            int   si = __shfl_sync(0xffffffffu, s, i);
            float ci = __shfl_sync(0xffffffffu, c, i);
            float4 f = feats[si * 32 + lane];
            acc.x = fmaf(ci, f.x, acc.x);
            acc.y = fmaf(ci, f.y, acc.y);
            acc.z = fmaf(ci, f.z, acc.z);
            acc.w = fmaf(ci, f.w, acc.w);
        }
    }
    ((float4*)g_agg)[v * 32 + lane] = acc;
}

// ======================= mma.sync bf16x3 GEMM ===============================
// out = rst@Wmsg^T + feats@Wskip^T + bias. Virtual A = [rst | feats] (N x 256).
// K processed in 4 chunks of 64. 3-term bf16 split for fp32-grade accuracy.
// Block: 128 rows x 128 cols out, 8 warps (4 along M x 2 along N).

#define OFF_AH 0
#define OFF_AL 16384
#define OFF_BH 32768
#define OFF_BL 49152
#define OFF_WE 65536
#define OFF_BE 67584
#define OFF_BIAS 68096
#define SMEM_TOT 68608

__device__ __forceinline__ void ldmx4(uint32_t addr, uint32_t& r0, uint32_t& r1,
                                      uint32_t& r2, uint32_t& r3) {
    asm volatile("ldmatrix.sync.aligned.m8n8.x4.shared.b16 {%0,%1,%2,%3}, [%4];"
                 : "=r"(r0), "=r"(r1), "=r"(r2), "=r"(r3) : "r"(addr));
}
__device__ __forceinline__ void mma16816(float* c, const uint32_t* a,
                                         uint32_t b0, uint32_t b1) {
    asm volatile(
        "mma.sync.aligned.m16n8k16.row.col.f32.bf16.bf16.f32 "
        "{%0,%1,%2,%3}, {%4,%5,%6,%7}, {%8,%9}, {%0,%1,%2,%3};"
        : "+f"(c[0]), "+f"(c[1]), "+f"(c[2]), "+f"(c[3])
        : "r"(a[0]), "r"(a[1]), "r"(a[2]), "r"(a[3]), "r"(b0), "r"(b1));
}

__global__ void __launch_bounds__(256, 2)
k_gemm_mma(const float* __restrict__ feats,
           const float4* __restrict__ Wedge, const float* __restrict__ bedge,
           const float* __restrict__ bmsg, const float* __restrict__ bskip,
           float* __restrict__ C, int n) {
    extern __shared__ uint8_t sm[];
    uint32_t sb = smem_u32(sm);
    int tid = threadIdx.x;
    int lane = tid & 31;
    int wid = tid >> 5;
    int wm = wid & 3;          // M slab: rows wm*32 .. +31
    int wn = wid >> 2;         // N slab: cols wn*64 .. +63

    // stage constants
    if (tid < DD) {
        ((float4*)(sm + OFF_WE))[tid] = Wedge[tid];
        ((float*)(sm + OFF_BE))[tid] = bedge[tid];
        ((float*)(sm + OFF_BIAS))[tid] = bmsg[tid] + bskip[tid];
    }

    // per-thread A-convert coords: row = tid/2, half = tid&1 (32 cols)
    int row = tid >> 1;
    int half = tid & 1;
    int grow = blockIdx.x * 128 + row;
    bool inb = grow < n;
    float4 efs = inb ? g_efsum[grow] : make_float4(0.f, 0.f, 0.f, 0.f);
    float ind = inb ? (float)g_indeg[grow] : 0.f;
    float nrm = inb ? g_norm[grow] : 0.f;

    const float4* agg4 = (const float4*)g_agg;
    const float4* fts4 = (const float4*)feats;
    const float4* sWe = (const float4*)(sm + OFF_WE);
    const float*  sBe = (const float*)(sm + OFF_BE);

    float acc[2][8][4];
#pragma unroll
    for (int mt = 0; mt < 2; mt++)
#pragma unroll
        for (int nf = 0; nf < 8; nf++)
#pragma unroll
            for (int e = 0; e < 4; e++) acc[mt][nf][e] = 0.f;

    // ldmatrix lane address components
    int aRow = lane & 15;
    int aSeg = lane >> 4;                  // 0/1 -> k +0 / +8
    int bq = lane >> 3;
    int bRowOff = ((bq >> 1) << 3) + (lane & 7);
    int bColSeg = bq & 1;

    for (int kc = 0; kc < 4; kc++) {
        __syncthreads();
        int phase = kc >> 1;
        int kc2 = kc & 1;
        // ---- B copy: 32KB prepacked (hi+lo) straight into smem image ----
        {
            const float4* src = (const float4*)(g_Bt + kc * 32768);
            float4* dst = (float4*)(sm + OFF_BH);
#pragma unroll
            for (int i = 0; i < 8; i++) dst[tid + i * 256] = src[tid + i * 256];
        }
        // ---- A convert -> bf16 hi/lo tiles ----
#pragma unroll
        for (int i = 0; i < 8; i++) {
            int c = half * 32 + i * 4;
            int gcol = kc2 * 64 + c;
            float v[4];
            if (phase == 0) {
                float4 a = inb ? agg4[grow * 32 + (gcol >> 2)] : make_float4(0, 0, 0, 0);
                float4 f = inb ? fts4[grow * 32 + (gcol >> 2)] : make_float4(0, 0, 0, 0);
                float av[4] = {a.x, a.y, a.z, a.w};
                float fv[4] = {f.x, f.y, f.z, f.w};
#pragma unroll
                for (int e = 0; e < 4; e++) {
                    float4 w = sWe[gcol + e];
                    float wef = w.x * efs.x + w.y * efs.y + w.z * efs.z + w.w * efs.w;
                    v[e] = (av[e] + wef + ind * (sBe[gcol + e] + fv[e] * nrm)) * nrm;
                }
            } else {
                float4 f = inb ? fts4[grow * 32 + (gcol >> 2)] : make_float4(0, 0, 0, 0);
                v[0] = f.x; v[1] = f.y; v[2] = f.z; v[3] = f.w;
            }
#pragma unroll
            for (int p = 0; p < 2; p++) {
                float v0 = v[2 * p], v1 = v[2 * p + 1];
                __nv_bfloat16 h0 = __float2bfloat16(v0), h1 = __float2bfloat16(v1);
                float l0 = v0 - __bfloat162float(h0), l1 = v1 - __bfloat162float(h1);
                __nv_bfloat16 q0 = __float2bfloat16(l0), q1 = __float2bfloat16(l1);
                uint32_t hw = (uint32_t)__bfloat16_as_ushort(h0) |
                              ((uint32_t)__bfloat16_as_ushort(h1) << 16);
                uint32_t lw = (uint32_t)__bfloat16_as_ushort(q0) |
                              ((uint32_t)__bfloat16_as_ushort(q1) << 16);
                uint32_t off = swz(row, c + 2 * p);
                *(uint32_t*)(sm + OFF_AH + off) = hw;
                *(uint32_t*)(sm + OFF_AL + off) = lw;
            }
        }
        __syncthreads();

        // ---- MMA over 4 k16 steps ----
#pragma unroll
        for (int ks = 0; ks < 4; ks++) {
            uint32_t ah[2][4], al[2][4];
#pragma unroll
            for (int mt = 0; mt < 2; mt++) {
                int r = wm * 32 + mt * 16 + aRow;
                int col = ks * 16 + aSeg * 8;
                uint32_t off = (uint32_t)(r * 128 + ((((col >> 3) ^ (r & 7)) << 4)));
                ldmx4(sb + OFF_AH + off, ah[mt][0], ah[mt][1], ah[mt][2], ah[mt][3]);
                ldmx4(sb + OFF_AL + off, al[mt][0], al[mt][1], al[mt][2], al[mt][3]);
            }
#pragma unroll
            for (int ntp = 0; ntp < 4; ntp++) {
                int r = wn * 64 + ntp * 16 + bRowOff;
                int col = ks * 16 + bColSeg * 8;
                uint32_t off = (uint32_t)(r * 128 + ((((col >> 3) ^ (r & 7)) << 4)));
                uint32_t bh[4], bl[4];
                ldmx4(sb + OFF_BH + off, bh[0], bh[1], bh[2], bh[3]);
                ldmx4(sb + OFF_BL + off, bl[0], bl[1], bl[2], bl[3]);
#pragma unroll
                for (int mt = 0; mt < 2; mt++) {
                    mma16816(acc[mt][ntp * 2], ah[mt], bh[0], bh[1]);
                    mma16816(acc[mt][ntp * 2], ah[mt], bl[0], bl[1]);
                    mma16816(acc[mt][ntp * 2], al[mt], bh[0], bh[1]);
                    mma16816(acc[mt][ntp * 2 + 1], ah[mt], bh[2], bh[3]);
                    mma16816(acc[mt][ntp * 2 + 1], ah[mt], bl[2], bl[3]);
                    mma16816(acc[mt][ntp * 2 + 1], al[mt], bh[2], bh[3]);
                }
            }
        }
    }

    // ---- epilogue ----
    const float* sBias = (const float*)(sm + OFF_BIAS);
#pragma unroll
    for (int mt = 0; mt < 2; mt++) {
        int r0 = blockIdx.x * 128 + wm * 32 + mt * 16 + (lane >> 2);
#pragma unroll
        for (int nf = 0; nf < 8; nf++) {
            int col = wn * 64 + nf * 8 + 2 * (lane & 3);
            float bx = sBias[col], by = sBias[col + 1];
            if (r0 < n) {
                float2 o = make_float2(acc[mt][nf][0] + bx, acc[mt][nf][1] + by);
                *(float2*)(C + r0 * DD + col) = o;
            }
            if (r0 + 8 < n) {
                float2 o = make_float2(acc[mt][nf][2] + bx, acc[mt][nf][3] + by);
                *(float2*)(C + (r0 + 8) * DD + col) = o;
            }
        }
    }
}

extern "C" void kernel_launch(void* const* d_in, const int* in_sizes, int n_in,
                              void* d_out, int out_size) {
    const float* feats      = (const float*)d_in[0];
    const float* edge_feats = (const float*)d_in[1];
    const int*   src_E      = (const int*)d_in[2];
    const int*   dst_E      = (const int*)d_in[3];
    const int*   src_acc    = (const int*)d_in[4];
    const int*   dst_acc    = (const int*)d_in[5];
    const float* W_skip     = (const float*)d_in[6];
    const float* b_skip     = (const float*)d_in[7];
    const float* W_msg      = (const float*)d_in[8];
    const float* b_msg      = (const float*)d_in[9];
    const float* W_edge     = (const float*)d_in[10];
    const float* b_edge     = (const float*)d_in[11];
    const float* W_att      = (const float*)d_in[12];
    const float* b_att      = (const float*)d_in[13];
    float* out = (float*)d_out;

    int n  = in_sizes[0] / DD;
    int eM = in_sizes[2];
    int eA = in_sizes[4];
    int nb = (n + 255) / 256;

    static int smem_set = 0;
    if (!smem_set) {
        cudaFuncSetAttribute(k_gemm_mma, cudaFuncAttributeMaxDynamicSharedMemorySize, SMEM_TOT);
        smem_set = 1;
    }

    k_init<<<128, 512>>>(n);
    k_prepB<<<64, 256>>>(W_msg, W_skip);
    k_count<<<2048, 512>>>(src_E, dst_E, (const float4*)edge_feats, dst_acc,
                           W_att, b_att, eM, eA);
    k_scan1<<<nb, 256>>>(n);
    k_scan2<<<1, NBMAX>>>(nb);
    k_scan3<<<nb, 256>>>(n);
    k_fill<<<(eM + eA + 255) / 256, 256>>>(src_E, dst_E, src_acc, dst_acc, b_att, eM, eA);
    k_gather<<<(n * 32 + 255) / 256, 256>>>((const float4*)feats, n);
    k_gemm_mma<<<(n + 127) / 128, 256, SMEM_TOT>>>(feats, (const float4*)W_edge, b_edge,
                                                   b_msg, b_skip, out, n);
}

// round 5
// speedup vs baseline: 2.1649x; 1.1024x over previous
#include <cuda_runtime.h>
#include <cuda_bf16.h>
#include <cuda_fp16.h>
#include <math.h>
#include <cstdint>

#define NN 100000
#define DD 128
#define EMAXM 1600000
#define EMAXT 1800000
#define NBMAX 512

// ---- static scratch (no allocation allowed) ----
__device__ float  g_agg[NN * DD];
__device__ float  g_norm[NN];
__device__ int    g_deg[NN];
__device__ int    g_indeg[NN];
__device__ float4 g_efsum[NN];
__device__ int    g_off[NN];
__device__ int    g_cursor[NN];
__device__ int    g_bsum[NBMAX];
__device__ int    g_boff[NBMAX];
__device__ float  g_att[EMAXM];
__device__ int2   g_edge[EMAXT];          // CSR: {src, coef} grouped by dst
__device__ __align__(16) __half2 g_h16[NN * 64];   // fp16 copy of feats
__device__ __align__(16) uint8_t g_Bt[4 * 32768];  // prepacked B tiles

__device__ __forceinline__ void red_add_v4(float* p, float x, float y, float z, float w) {
    asm volatile("red.global.add.v4.f32 [%0], {%1,%2,%3,%4};"
                 :: "l"(p), "f"(x), "f"(y), "f"(z), "f"(w) : "memory");
}
__device__ __forceinline__ uint32_t smem_u32(const void* p) {
    uint32_t a;
    asm("{ .reg .u64 t; cvta.to.shared.u64 t, %1; cvt.u32.u64 %0, t; }" : "=r"(a) : "l"(p));
    return a;
}
// swizzled byte offset inside a 128-row x 64-col bf16 tile (128B rows)
__device__ __forceinline__ uint32_t swz(int row, int col) {
    return (uint32_t)(row * 128 + ((((col >> 3) ^ (row & 7)) << 4)) + ((col & 7) << 1));
}

// ======================= graph-prep kernels =============
__global__ void k_init(int n) {
    int stride = gridDim.x * blockDim.x;
    for (int i = blockIdx.x * blockDim.x + threadIdx.x; i < n; i += stride) {
        g_deg[i] = 0;
        g_indeg[i] = 0;
        g_efsum[i] = make_float4(0.f, 0.f, 0.f, 0.f);
    }
}

// fp32 feats -> fp16 packed copy
__global__ void k_h16(const float4* __restrict__ feats, int n) {
    int i = blockIdx.x * blockDim.x + threadIdx.x;
    int tot = n * 32;
    if (i >= tot) return;
    float4 f = feats[i];
    __half2 a = __floats2half2_rn(f.x, f.y);
    __half2 b = __floats2half2_rn(f.z, f.w);
    g_h16[i * 2] = a;
    g_h16[i * 2 + 1] = b;
}

__global__ void k_prepB(const float* __restrict__ Wmsg, const float* __restrict__ Wskip) {
    int w = blockIdx.x * blockDim.x + threadIdx.x;
    if (w >= 16384) return;
    int phase = w >> 13;
    int j = (w >> 6) & 127;
    int kp = w & 63;
    int k = kp * 2;
    const float* W = phase ? Wskip : Wmsg;
    float v0 = W[j * DD + k], v1 = W[j * DD + k + 1];
    __nv_bfloat16 h0 = __float2bfloat16(v0), h1 = __float2bfloat16(v1);
    float l0 = v0 - __bfloat162float(h0), l1 = v1 - __bfloat162float(h1);
    __nv_bfloat16 q0 = __float2bfloat16(l0), q1 = __float2bfloat16(l1);
    uint32_t hw = (uint32_t)__bfloat16_as_ushort(h0) | ((uint32_t)__bfloat16_as_ushort(h1) << 16);
    uint32_t lw = (uint32_t)__bfloat16_as_ushort(q0) | ((uint32_t)__bfloat16_as_ushort(q1) << 16);
    int kc2 = k >> 6;
    int kin = k & 63;
    int tile = phase * 2 + kc2;
    uint32_t off = swz(j, kin);
    *(uint32_t*)(g_Bt + tile * 32768 + off) = hw;
    *(uint32_t*)(g_Bt + tile * 32768 + 16384 + off) = lw;
}

__global__ void k_count(const int* __restrict__ srcE, const int* __restrict__ dstE,
                        const float4* __restrict__ ef, const int* __restrict__ dstA,
                        const float* __restrict__ W_att, const float* __restrict__ b_att,
                        int eM, int eA) {
    int stride = gridDim.x * blockDim.x;
    int i0 = blockIdx.x * blockDim.x + threadIdx.x;
    float w0 = W_att[0], w1 = W_att[1], w2 = W_att[2], w3 = W_att[3], bb = b_att[0];
    for (int e = i0; e < eM; e += stride) {
        atomicAdd(&g_deg[srcE[e]], 1);
        int d = dstE[e];
        atomicAdd(&g_indeg[d], 1);
        float4 f = ef[e];
        red_add_v4((float*)&g_efsum[d], f.x, f.y, f.z, f.w);
        float x = w0 * f.x + w1 * f.y + w2 * f.z + w3 * f.w + bb;
        g_att[e] = 1.f / (1.f + __expf(-x));
    }
    for (int e = i0; e < eA; e += stride)
        atomicAdd(&g_indeg[dstA[e]], 1);
}

__global__ void k_scan1(int n) {
    int t = blockIdx.x * 256 + threadIdx.x;
    int v = (t < n) ? g_indeg[t] : 0;
    if (t < n) {
        int dg = g_deg[t];
        g_norm[t] = (dg > 0) ? rsqrtf((float)dg) : 0.f;
    }
    __shared__ int sh[256];
    sh[threadIdx.x] = v;
    __syncthreads();
    for (int o = 128; o > 0; o >>= 1) {
        if (threadIdx.x < o) sh[threadIdx.x] += sh[threadIdx.x + o];
        __syncthreads();
    }
    if (threadIdx.x == 0) g_bsum[blockIdx.x] = sh[0];
}

__global__ void k_scan2(int nb) {
    __shared__ int sh[NBMAX];
    int t = threadIdx.x;
    int v = (t < nb) ? g_bsum[t] : 0;
    sh[t] = v;
    __syncthreads();
    for (int o = 1; o < NBMAX; o <<= 1) {
        int x = (t >= o) ? sh[t - o] : 0;
        __syncthreads();
        sh[t] += x;
        __syncthreads();
    }
    if (t < nb) g_boff[t] = sh[t] - v;
}

__global__ void k_scan3(int n) {
    __shared__ int sh[256];
    int t = blockIdx.x * 256 + threadIdx.x;
    int v = (t < n) ? g_indeg[t] : 0;
    sh[threadIdx.x] = v;
    __syncthreads();
    for (int o = 1; o < 256; o <<= 1) {
        int x = (threadIdx.x >= o) ? sh[threadIdx.x - o] : 0;
        __syncthreads();
        sh[threadIdx.x] += x;
        __syncthreads();
    }
    if (t < n) {
        int off = sh[threadIdx.x] - v + g_boff[blockIdx.x];
        g_off[t] = off;
        g_cursor[t] = off;
    }
}

// fill CSR: record = {src, att * norm[src]} packed as int2
__global__ void k_fill(const int* __restrict__ srcE, const int* __restrict__ dstE,
                       const int* __restrict__ srcA, const int* __restrict__ dstA,
                       const float* __restrict__ b_att, int eM, int eA) {
    int i = blockIdx.x * blockDim.x + threadIdx.x;
    int tot = eM + eA;
    if (i >= tot) return;
    int s, d; float a;
    if (i < eM) {
        s = srcE[i]; d = dstE[i]; a = g_att[i];
    } else {
        int j = i - eM;
        s = srcA[j]; d = dstA[j];
        a = 1.f / (1.f + __expf(-b_att[0]));
    }
    float c = a * g_norm[s];
    int pos = atomicAdd(&g_cursor[d], 1);
    g_edge[pos] = make_int2(s, __float_as_int(c));
}

// gather from fp16 feats copy: warp per dst node, no atomics
__global__ void k_gather(int n) {
    int gtid = blockIdx.x * blockDim.x + threadIdx.x;
    int v = gtid >> 5;
    int lane = gtid & 31;
    if (v >= n) return;
    int off = g_off[v];
    int cnt = g_indeg[v];
    const uint2* h16 = (const uint2*)g_h16;     // [NN*32] : 4 halves each
    float4 acc = make_float4(0.f, 0.f, 0.f, 0.f);
    for (int base = 0; base < cnt; base += 32) {
        int m = cnt - base; if (m > 32) m = 32;
        int s = 0; float c = 0.f;
        if (lane < m) {
            int2 er = g_edge[off + base + lane];
            s = er.x;
            c = __int_as_float(er.y);
        }
#pragma unroll 4
        for (int i = 0; i < m; i++) {
            int   si = __shfl_sync(0xffffffffu, s, i);
            float ci = __shfl_sync(0xffffffffu, c, i);
            uint2 hv = h16[si * 32 + lane];
            float2 fa = __half22float2(*(__half2*)&hv.x);
            float2 fb = __half22float2(*(__half2*)&hv.y);
            acc.x = fmaf(ci, fa.x, acc.x);
            acc.y = fmaf(ci, fa.y, acc.y);
            acc.z = fmaf(ci, fb.x, acc.z);
            acc.w = fmaf(ci, fb.y, acc.w);
        }
    }
    ((float4*)g_agg)[v * 32 + lane] = acc;
}

// ======================= mma.sync bf16x3 GEMM (unchanged from R4) ===========
#define OFF_AH 0
#define OFF_AL 16384
#define OFF_BH 32768
#define OFF_BL 49152
#define OFF_WE 65536
#define OFF_BE 67584
#define OFF_BIAS 68096
#define SMEM_TOT 68608

__device__ __forceinline__ void ldmx4(uint32_t addr, uint32_t& r0, uint32_t& r1,
                                      uint32_t& r2, uint32_t& r3) {
    asm volatile("ldmatrix.sync.aligned.m8n8.x4.shared.b16 {%0,%1,%2,%3}, [%4];"
                 : "=r"(r0), "=r"(r1), "=r"(r2), "=r"(r3) : "r"(addr));
}
__device__ __forceinline__ void mma16816(float* c, const uint32_t* a,
                                         uint32_t b0, uint32_t b1) {
    asm volatile(
        "mma.sync.aligned.m16n8k16.row.col.f32.bf16.bf16.f32 "
        "{%0,%1,%2,%3}, {%4,%5,%6,%7}, {%8,%9}, {%0,%1,%2,%3};"
        : "+f"(c[0]), "+f"(c[1]), "+f"(c[2]), "+f"(c[3])
        : "r"(a[0]), "r"(a[1]), "r"(a[2]), "r"(a[3]), "r"(b0), "r"(b1));
}

__global__ void __launch_bounds__(256, 2)
k_gemm_mma(const float* __restrict__ feats,
           const float4* __restrict__ Wedge, const float* __restrict__ bedge,
           const float* __restrict__ bmsg, const float* __restrict__ bskip,
           float* __restrict__ C, int n) {
    extern __shared__ uint8_t sm[];
    uint32_t sb = smem_u32(sm);
    int tid = threadIdx.x;
    int lane = tid & 31;
    int wid = tid >> 5;
    int wm = wid & 3;
    int wn = wid >> 2;

    if (tid < DD) {
        ((float4*)(sm + OFF_WE))[tid] = Wedge[tid];
        ((float*)(sm + OFF_BE))[tid] = bedge[tid];
        ((float*)(sm + OFF_BIAS))[tid] = bmsg[tid] + bskip[tid];
    }

    int row = tid >> 1;
    int half = tid & 1;
    int grow = blockIdx.x * 128 + row;
    bool inb = grow < n;
    float4 efs = inb ? g_efsum[grow] : make_float4(0.f, 0.f, 0.f, 0.f);
    float ind = inb ? (float)g_indeg[grow] : 0.f;
    float nrm = inb ? g_norm[grow] : 0.f;

    const float4* agg4 = (const float4*)g_agg;
    const float4* fts4 = (const float4*)feats;
    const float4* sWe = (const float4*)(sm + OFF_WE);
    const float*  sBe = (const float*)(sm + OFF_BE);

    float acc[2][8][4];
#pragma unroll
    for (int mt = 0; mt < 2; mt++)
#pragma unroll
        for (int nf = 0; nf < 8; nf++)
#pragma unroll
            for (int e = 0; e < 4; e++) acc[mt][nf][e] = 0.f;

    int aRow = lane & 15;
    int aSeg = lane >> 4;
    int bq = lane >> 3;
    int bRowOff = ((bq >> 1) << 3) + (lane & 7);
    int bColSeg = bq & 1;

    for (int kc = 0; kc < 4; kc++) {
        __syncthreads();
        int phase = kc >> 1;
        int kc2 = kc & 1;
        {
            const float4* src = (const float4*)(g_Bt + kc * 32768);
            float4* dst = (float4*)(sm + OFF_BH);
#pragma unroll
            for (int i = 0; i < 8; i++) dst[tid + i * 256] = src[tid + i * 256];
        }
#pragma unroll
        for (int i = 0; i < 8; i++) {
            int c = half * 32 + i * 4;
            int gcol = kc2 * 64 + c;
            float v[4];
            if (phase == 0) {
                float4 a = inb ? agg4[grow * 32 + (gcol >> 2)] : make_float4(0, 0, 0, 0);
                float4 f = inb ? fts4[grow * 32 + (gcol >> 2)] : make_float4(0, 0, 0, 0);
                float av[4] = {a.x, a.y, a.z, a.w};
                float fv[4] = {f.x, f.y, f.z, f.w};
#pragma unroll
                for (int e = 0; e < 4; e++) {
                    float4 w = sWe[gcol + e];
                    float wef = w.x * efs.x + w.y * efs.y + w.z * efs.z + w.w * efs.w;
                    v[e] = (av[e] + wef + ind * (sBe[gcol + e] + fv[e] * nrm)) * nrm;
                }
            } else {
                float4 f = inb ? fts4[grow * 32 + (gcol >> 2)] : make_float4(0, 0, 0, 0);
                v[0] = f.x; v[1] = f.y; v[2] = f.z; v[3] = f.w;
            }
#pragma unroll
            for (int p = 0; p < 2; p++) {
                float v0 = v[2 * p], v1 = v[2 * p + 1];
                __nv_bfloat16 h0 = __float2bfloat16(v0), h1 = __float2bfloat16(v1);
                float l0 = v0 - __bfloat162float(h0), l1 = v1 - __bfloat162float(h1);
                __nv_bfloat16 q0 = __float2bfloat16(l0), q1 = __float2bfloat16(l1);
                uint32_t hw = (uint32_t)__bfloat16_as_ushort(h0) |
                              ((uint32_t)__bfloat16_as_ushort(h1) << 16);
                uint32_t lw = (uint32_t)__bfloat16_as_ushort(q0) |
                              ((uint32_t)__bfloat16_as_ushort(q1) << 16);
                uint32_t off = swz(row, c + 2 * p);
                *(uint32_t*)(sm + OFF_AH + off) = hw;
                *(uint32_t*)(sm + OFF_AL + off) = lw;
            }
        }
        __syncthreads();

#pragma unroll
        for (int ks = 0; ks < 4; ks++) {
            uint32_t ah[2][4], al[2][4];
#pragma unroll
            for (int mt = 0; mt < 2; mt++) {
                int r = wm * 32 + mt * 16 + aRow;
                int col = ks * 16 + aSeg * 8;
                uint32_t off = (uint32_t)(r * 128 + ((((col >> 3) ^ (r & 7)) << 4)));
                ldmx4(sb + OFF_AH + off, ah[mt][0], ah[mt][1], ah[mt][2], ah[mt][3]);
                ldmx4(sb + OFF_AL + off, al[mt][0], al[mt][1], al[mt][2], al[mt][3]);
            }
#pragma unroll
            for (int ntp = 0; ntp < 4; ntp++) {
                int r = wn * 64 + ntp * 16 + bRowOff;
                int col = ks * 16 + bColSeg * 8;
                uint32_t off = (uint32_t)(r * 128 + ((((col >> 3) ^ (r & 7)) << 4)));
                uint32_t bh[4], bl[4];
                ldmx4(sb + OFF_BH + off, bh[0], bh[1], bh[2], bh[3]);
                ldmx4(sb + OFF_BL + off, bl[0], bl[1], bl[2], bl[3]);
#pragma unroll
                for (int mt = 0; mt < 2; mt++) {
                    mma16816(acc[mt][ntp * 2], ah[mt], bh[0], bh[1]);
                    mma16816(acc[mt][ntp * 2], ah[mt], bl[0], bl[1]);
                    mma16816(acc[mt][ntp * 2], al[mt], bh[0], bh[1]);
                    mma16816(acc[mt][ntp * 2 + 1], ah[mt], bh[2], bh[3]);
                    mma16816(acc[mt][ntp * 2 + 1], ah[mt], bl[2], bl[3]);
                    mma16816(acc[mt][ntp * 2 + 1], al[mt], bh[2], bh[3]);
                }
            }
        }
    }

    const float* sBias = (const float*)(sm + OFF_BIAS);
#pragma unroll
    for (int mt = 0; mt < 2; mt++) {
        int r0 = blockIdx.x * 128 + wm * 32 + mt * 16 + (lane >> 2);
#pragma unroll
        for (int nf = 0; nf < 8; nf++) {
            int col = wn * 64 + nf * 8 + 2 * (lane & 3);
            float bx = sBias[col], by = sBias[col + 1];
            if (r0 < n) {
                float2 o = make_float2(acc[mt][nf][0] + bx, acc[mt][nf][1] + by);
                *(float2*)(C + r0 * DD + col) = o;
            }
            if (r0 + 8 < n) {
                float2 o = make_float2(acc[mt][nf][2] + bx, acc[mt][nf][3] + by);
                *(float2*)(C + (r0 + 8) * DD + col) = o;
            }
        }
    }
}

extern "C" void kernel_launch(void* const* d_in, const int* in_sizes, int n_in,
                              void* d_out, int out_size) {
    const float* feats      = (const float*)d_in[0];
    const float* edge_feats = (const float*)d_in[1];
    const int*   src_E      = (const int*)d_in[2];
    const int*   dst_E      = (const int*)d_in[3];
    const int*   src_acc    = (const int*)d_in[4];
    const int*   dst_acc    = (const int*)d_in[5];
    const float* W_skip     = (const float*)d_in[6];
    const float* b_skip     = (const float*)d_in[7];
    const float* W_msg      = (const float*)d_in[8];
    const float* b_msg      = (const float*)d_in[9];
    const float* W_edge     = (const float*)d_in[10];
    const float* b_edge     = (const float*)d_in[11];
    const float* W_att      = (const float*)d_in[12];
    const float* b_att      = (const float*)d_in[13];
    float* out = (float*)d_out;

    int n  = in_sizes[0] / DD;
    int eM = in_sizes[2];
    int eA = in_sizes[4];
    int nb = (n + 255) / 256;

    static int smem_set = 0;
    if (!smem_set) {
        cudaFuncSetAttribute(k_gemm_mma, cudaFuncAttributeMaxDynamicSharedMemorySize, SMEM_TOT);
        smem_set = 1;
    }

    k_init<<<128, 512>>>(n);
    k_h16<<<(n * 32 + 255) / 256, 256>>>((const float4*)feats, n);
    k_prepB<<<64, 256>>>(W_msg, W_skip);
    k_count<<<2048, 512>>>(src_E, dst_E, (const float4*)edge_feats, dst_acc,
                           W_att, b_att, eM, eA);
    k_scan1<<<nb, 256>>>(n);
    k_scan2<<<1, NBMAX>>>(nb);
    k_scan3<<<nb, 256>>>(n);
    k_fill<<<(eM + eA + 255) / 256, 256>>>(src_E, dst_E, src_acc, dst_acc, b_att, eM, eA);
    k_gather<<<(n * 32 + 255) / 256, 256>>>(n);
    k_gemm_mma<<<(n + 127) / 128, 256, SMEM_TOT>>>(feats, (const float4*)W_edge, b_edge,
                                                   b_msg, b_skip, out, n);
}